// round 14
// baseline (speedup 1.0000x reference)
#include <cuda_runtime.h>
#include <cuda_bf16.h>
#include <cstdint>

#define DEVFN __device__ __forceinline__

constexpr int BN = 16;      // batch
constexpr int CI = 64;      // in channels
constexpr int CO = 64;      // out channels
constexpr int HW = 4096;    // 64x64
constexpr int OC = 18;      // offset channels

// Scratch (static device memory; zero-initialized at module load)
__device__ __align__(16) float g_xt [BN * HW * CI];       // x in NHWC
__device__ __align__(16) __nv_bfloat16 g_wbh[9 * 4096];   // w_dcn hi, per-tap SW128-swizzled [co][cin]
__device__ __align__(16) __nv_bfloat16 g_wbl[9 * 4096];   // w_dcn lo
__device__ __align__(16) __nv_bfloat16 g_wobh[9 * 2048];  // w_off hi, per-tap SW128 [oc(32,pad0)][cin]
__device__ __align__(16) __nv_bfloat16 g_wobl[9 * 2048];  // w_off lo
__device__ __align__(16) float4 g_cfw[BN * HW * 9];       // bilinear weights per (pix,tap)
__device__ __align__(16) int4   g_cfi[BN * HW * 9];       // clamped corner base offsets

DEVFN uint32_t smem_u32(const void* p) {
    uint32_t a;
    asm("{ .reg .u64 t; cvta.to.shared.u64 t, %1; cvt.u32.u64 %0, t; }" : "=r"(a) : "l"(p));
    return a;
}
// ---- ldmatrix / mma.sync (sm_80+ PTX, valid on plain sm_103 target) ----
DEVFN void ldm_x4(uint32_t* r, uint32_t addr) {
    asm volatile("ldmatrix.sync.aligned.m8n8.x4.shared.b16 {%0,%1,%2,%3}, [%4];"
                 : "=r"(r[0]), "=r"(r[1]), "=r"(r[2]), "=r"(r[3]) : "r"(addr));
}
DEVFN void ldm_x2(uint32_t* r, uint32_t addr) {
    asm volatile("ldmatrix.sync.aligned.m8n8.x2.shared.b16 {%0,%1}, [%2];"
                 : "=r"(r[0]), "=r"(r[1]) : "r"(addr));
}
DEVFN void mma_bf16(float* d, const uint32_t* a, const uint32_t* b) {
    asm volatile("mma.sync.aligned.m16n8k16.row.col.f32.bf16.bf16.f32 "
                 "{%0,%1,%2,%3}, {%4,%5,%6,%7}, {%8,%9}, {%0,%1,%2,%3};"
                 : "+f"(d[0]), "+f"(d[1]), "+f"(d[2]), "+f"(d[3])
                 : "r"(a[0]), "r"(a[1]), "r"(a[2]), "r"(a[3]), "r"(b[0]), "r"(b[1]));
}
DEVFN uint32_t sw128(uint32_t byte) { return byte ^ ((byte >> 3) & 0x70); }
DEVFN void split_store(char* smem_base, uint32_t sw, float2 v, int loOff) {
    __nv_bfloat162 h2 = __float22bfloat162_rn(v);
    float2 fh = __bfloat1622float2(h2);
    __nv_bfloat162 l2 = __float22bfloat162_rn(make_float2(v.x - fh.x, v.y - fh.y));
    *(uint32_t*)(smem_base + sw)         = *(uint32_t*)&h2;
    *(uint32_t*)(smem_base + loOff + sw) = *(uint32_t*)&l2;
}

// ---------------------------------------------------------------------------
// Weight prepack: bf16 hi/lo split + SW128 pre-swizzle for both convs.
// ---------------------------------------------------------------------------
__global__ void k_prepack(const float* __restrict__ wdcn, const float* __restrict__ woff) {
    int i = blockIdx.x * blockDim.x + threadIdx.x;
    if (i < 9 * 4096) {
        int t = i >> 12, r = i & 4095;
        int co = r >> 6, cin = r & 63;
        float w = wdcn[(co * CI + cin) * 9 + t];
        __nv_bfloat16 hi = __float2bfloat16(w);
        __nv_bfloat16 lo = __float2bfloat16(w - __bfloat162float(hi));
        uint32_t sw = sw128((uint32_t)(co * 128 + cin * 2));
        g_wbh[t * 4096 + (sw >> 1)] = hi;
        g_wbl[t * 4096 + (sw >> 1)] = lo;
    }
    int j = i - 9 * 4096;
    if (j >= 0 && j < 9 * OC * 64) {
        int t  = j / (OC * 64);
        int r  = j - t * (OC * 64);
        int oc = r >> 6, cin = r & 63;
        float w = woff[(oc * CI + cin) * 9 + t];
        __nv_bfloat16 hi = __float2bfloat16(w);
        __nv_bfloat16 lo = __float2bfloat16(w - __bfloat162float(hi));
        uint32_t sw = sw128((uint32_t)(oc * 128 + cin * 2));
        g_wobh[t * 2048 + (sw >> 1)] = hi;
        g_wobl[t * 2048 + (sw >> 1)] = lo;
    }
}

// ---------------------------------------------------------------------------
// NCHW -> NHWC transpose
// ---------------------------------------------------------------------------
__global__ void k_transpose(const float* __restrict__ x) {
    __shared__ float s[32][33];
    int b  = blockIdx.z;
    int c0 = blockIdx.y * 32;
    int p0 = blockIdx.x * 32;
    int tx = threadIdx.x, ty = threadIdx.y;
    const float* xb = x + (size_t)b * CI * HW;
#pragma unroll
    for (int i = 0; i < 4; i++)
        s[ty + 8 * i][tx] = xb[(size_t)(c0 + ty + 8 * i) * HW + p0 + tx];
    __syncthreads();
    float* xtb = g_xt + (size_t)b * HW * CI;
#pragma unroll
    for (int i = 0; i < 4; i++)
        xtb[(size_t)(p0 + ty + 8 * i) * CI + c0 + tx] = s[tx][ty + 8 * i];
}

// ---------------------------------------------------------------------------
// Offset conv (split-bf16 mma, N padded 18->32) + fused bilinear coeff
// computation. CTA = 256 thr, 128 px. Writes g_cfw/g_cfi directly.
// smem: Ah[0,16K) Al[16K,32K) Bh[32K,36K) Bl[36K,40K); reused for epilogue.
// ---------------------------------------------------------------------------
__global__ __launch_bounds__(256) void k_offcoef(const float* __restrict__ boff) {
    __shared__ __align__(128) char smem[40960];
    uint32_t sb = smem_u32(smem);
    int tid = threadIdx.x, wid = tid >> 5, lane = tid & 31;
    int base = blockIdx.x * 128;
    int b    = base >> 12;
    int prow = base & 4095;
    const float* xtb = g_xt + (size_t)b * HW * CI;

    float acc[4][4];
#pragma unroll
    for (int ni = 0; ni < 4; ni++)
#pragma unroll
        for (int e = 0; e < 4; e++) acc[ni][e] = 0.f;

    for (int t = 0; t < 9; t++) {
        // ---- stage B hi/lo: 32x128B each = 256 uint4 ----
        ((uint4*)(smem + 32768))[tid] = ((const uint4*)(g_wobh + t * 2048))[tid];
        ((uint4*)(smem + 36864))[tid] = ((const uint4*)(g_wobl + t * 2048))[tid];
        int dy = t / 3 - 1;
        int dx = t - (t / 3) * 3 - 1;
        // ---- integer-tap gather: warp w -> pixels w*16..+15, lane = ch-pair ----
#pragma unroll 4
        for (int i = 0; i < 16; i++) {
            int p  = wid * 16 + i;
            int pp = prow + p;
            int y  = (pp >> 6) + dy;
            int x  = (pp & 63) + dx;
            float2 v = make_float2(0.f, 0.f);
            if (((unsigned)y < 64u) && ((unsigned)x < 64u))
                v = *((const float2*)(xtb + (((y << 6) + x) << 6)) + lane);
            split_store(smem, sw128((uint32_t)(p * 128 + lane * 4)), v, 16384);
        }
        __syncthreads();
        // ---- warp GEMM: 16px x 32co, 4 k16 chunks, 3 split passes ----
#pragma unroll
        for (int k16 = 0; k16 < 4; k16++) {
            uint32_t ah[4], al[4];
            {
                int row = wid * 16 + (lane & 15);
                uint32_t byte = sw128((uint32_t)(row * 128 + k16 * 32 + ((lane >> 4) << 4)));
                ldm_x4(ah, sb + byte);
                ldm_x4(al, sb + 16384 + byte);
            }
            uint32_t bh[4][2], bl[4][2];
#pragma unroll
            for (int ni = 0; ni < 4; ni++) {
                int n = ni * 8 + (lane & 7);
                uint32_t byte = sw128((uint32_t)(n * 128 + k16 * 32 + (((lane >> 3) & 1) << 4)));
                ldm_x2(bh[ni], sb + 32768 + byte);
                ldm_x2(bl[ni], sb + 36864 + byte);
            }
#pragma unroll
            for (int ni = 0; ni < 4; ni++) {
                mma_bf16(acc[ni], ah, bh[ni]);
                mma_bf16(acc[ni], al, bh[ni]);
                mma_bf16(acc[ni], ah, bl[ni]);
            }
        }
        __syncthreads();
    }
    // ---- bounce offsets to smem [px][36] ----
    float* sAcc = (float*)smem;
    int r = lane >> 2, g = lane & 3;
#pragma unroll
    for (int ni = 0; ni < 4; ni++) {
        int co = ni * 8 + g * 2;
        int px = wid * 16 + r;
        sAcc[px * 36 + co]           = acc[ni][0];
        sAcc[px * 36 + co + 1]       = acc[ni][1];
        sAcc[(px + 8) * 36 + co]     = acc[ni][2];
        sAcc[(px + 8) * 36 + co + 1] = acc[ni][3];
    }
    __syncthreads();
    // ---- fused coeff: thread p < 128 handles its pixel's 9 taps ----
    if (tid < 128) {
        int p    = tid;
        int gpix = base + p;
        int pp   = prow + p;
        float fho = (float)(pp >> 6), fwo = (float)(pp & 63);
#pragma unroll
        for (int t = 0; t < 9; t++) {
            float oy = sAcc[p * 36 + 2 * t]     + boff[2 * t];
            float ox = sAcc[p * 36 + 2 * t + 1] + boff[2 * t + 1];
            float py  = fho + (float)(t / 3 - 1) + oy;
            float pxx = fwo + (float)(t % 3 - 1) + ox;
            float y0f = floorf(py), x0f = floorf(pxx);
            float fy = py - y0f, fx = pxx - x0f;
            int y0 = (int)y0f, x0 = (int)x0f;
            float vy0 = ((unsigned)y0 < 64u) ? 1.f : 0.f;
            float vy1 = ((unsigned)(y0 + 1) < 64u) ? 1.f : 0.f;
            float vx0 = ((unsigned)x0 < 64u) ? 1.f : 0.f;
            float vx1 = ((unsigned)(x0 + 1) < 64u) ? 1.f : 0.f;
            float gy0 = 1.f - fy, gx0 = 1.f - fx;
            g_cfw[gpix * 9 + t] = make_float4(gy0 * gx0 * vy0 * vx0, gy0 * fx * vy0 * vx1,
                                              fy * gx0 * vy1 * vx0,  fy * fx * vy1 * vx1);
            int yc0 = min(max(y0, 0), 63),     yc1 = min(max(y0 + 1, 0), 63);
            int xc0 = min(max(x0, 0), 63),     xc1 = min(max(x0 + 1, 0), 63);
            g_cfi[gpix * 9 + t] = make_int4((((yc0 << 6) + xc0) << 6), (((yc0 << 6) + xc1) << 6),
                                            (((yc1 << 6) + xc0) << 6), (((yc1 << 6) + xc1) << 6));
        }
    }
}

// ---------------------------------------------------------------------------
// Deformable conv: split-bf16 mma.sync GEMM. CTA = 256 thr, 128 px x 64 co.
// smem: Ah[0,16K) Al[16K,32K) Bh[32K,40K) Bl[40K,48K); reused for epilogue.
// ---------------------------------------------------------------------------
__global__ __launch_bounds__(256) void k_deform(const float* __restrict__ bdcn,
                                                float* __restrict__ out) {
    __shared__ __align__(128) char smem[49152];
    uint32_t sb = smem_u32(smem);
    int tid = threadIdx.x, wid = tid >> 5, lane = tid & 31;
    int base = blockIdx.x * 128;
    int b    = base >> 12;
    int prow = base & 4095;
    const float* xtb = g_xt + (size_t)b * HW * CI;
    int wm = wid >> 1, wn = wid & 1;          // warp grid 4(m) x 2(n)
    int mbase = wm * 32, nbase = wn * 32;

    float acc[2][4][4];
#pragma unroll
    for (int mi = 0; mi < 2; mi++)
#pragma unroll
        for (int ni = 0; ni < 4; ni++)
#pragma unroll
            for (int e = 0; e < 4; e++) acc[mi][ni][e] = 0.f;

    for (int t = 0; t < 9; t++) {
        // ---- stage B hi/lo (pre-swizzled; 512+512 uint4) ----
        {
            const uint4* sh = (const uint4*)(g_wbh + t * 4096);
            const uint4* sl = (const uint4*)(g_wbl + t * 4096);
            ((uint4*)(smem + 32768))[tid]       = sh[tid];
            ((uint4*)(smem + 32768))[tid + 256] = sh[tid + 256];
            ((uint4*)(smem + 40960))[tid]       = sl[tid];
            ((uint4*)(smem + 40960))[tid + 256] = sl[tid + 256];
        }
        // ---- bilinear gather: warp w -> pixels w*16..+15, lane = ch-pair ----
#pragma unroll 2
        for (int i = 0; i < 16; i++) {
            int p = wid * 16 + i;
            int ci = (base + p) * 9 + t;
            float4 cw = g_cfw[ci];
            int4  ii = g_cfi[ci];
            float2 v00 = *((const float2*)(xtb + ii.x) + lane);
            float2 v01 = *((const float2*)(xtb + ii.y) + lane);
            float2 v10 = *((const float2*)(xtb + ii.z) + lane);
            float2 v11 = *((const float2*)(xtb + ii.w) + lane);
            float2 v;
            v.x = cw.x * v00.x + cw.y * v01.x + cw.z * v10.x + cw.w * v11.x;
            v.y = cw.x * v00.y + cw.y * v01.y + cw.z * v10.y + cw.w * v11.y;
            split_store(smem, sw128((uint32_t)(p * 128 + lane * 4)), v, 16384);
        }
        __syncthreads();
        // ---- warp GEMM: 4 k16 chunks, 3 split passes on shared accumulators ----
#pragma unroll
        for (int k16 = 0; k16 < 4; k16++) {
            uint32_t ah[2][4], al[2][4];
#pragma unroll
            for (int mi = 0; mi < 2; mi++) {
                int row = mbase + mi * 16 + (lane & 15);
                uint32_t byte = sw128((uint32_t)(row * 128 + k16 * 32 + ((lane >> 4) << 4)));
                ldm_x4(ah[mi], sb + byte);
                ldm_x4(al[mi], sb + 16384 + byte);
            }
            uint32_t bh[4][2], bl[4][2];
#pragma unroll
            for (int ni = 0; ni < 4; ni++) {
                int n = nbase + ni * 8 + (lane & 7);
                uint32_t byte = sw128((uint32_t)(n * 128 + k16 * 32 + (((lane >> 3) & 1) << 4)));
                ldm_x2(bh[ni], sb + 32768 + byte);
                ldm_x2(bl[ni], sb + 40960 + byte);
            }
#pragma unroll
            for (int mi = 0; mi < 2; mi++)
#pragma unroll
                for (int ni = 0; ni < 4; ni++) {
                    mma_bf16(acc[mi][ni], ah[mi], bh[ni]);
                    mma_bf16(acc[mi][ni], al[mi], bh[ni]);
                    mma_bf16(acc[mi][ni], ah[mi], bl[ni]);
                }
        }
        __syncthreads();
    }
    // ---- epilogue: bounce acc through smem [co][132] for coalesced stores ----
    float* sAcc = (float*)smem;
    int r = lane >> 2, g = lane & 3;
#pragma unroll
    for (int mi = 0; mi < 2; mi++)
#pragma unroll
        for (int ni = 0; ni < 4; ni++) {
            int co = nbase + ni * 8 + g * 2;
            int px = mbase + mi * 16 + r;
            sAcc[co * 132 + px]             = acc[mi][ni][0];
            sAcc[(co + 1) * 132 + px]       = acc[mi][ni][1];
            sAcc[co * 132 + px + 8]         = acc[mi][ni][2];
            sAcc[(co + 1) * 132 + px + 8]   = acc[mi][ni][3];
        }
    __syncthreads();
    float* ob = out + (size_t)b * CO * HW + prow;
#pragma unroll
    for (int it = 0; it < 8; it++) {
        int idx = tid + 256 * it;          // 2048 float4 total
        int row = idx >> 5, c4 = idx & 31;
        float4 v = *(float4*)(sAcc + row * 132 + c4 * 4);
        float bias = bdcn[row];
        v.x += bias; v.y += bias; v.z += bias; v.w += bias;
        *(float4*)(ob + (size_t)row * HW + c4 * 4) = v;
    }
}

// ---------------------------------------------------------------------------
extern "C" void kernel_launch(void* const* d_in, const int* in_sizes, int n_in,
                              void* d_out, int out_size) {
    const float* x     = (const float*)d_in[0];
    const float* w_off = (const float*)d_in[1];
    const float* b_off = (const float*)d_in[2];
    const float* w_dcn = (const float*)d_in[3];
    const float* b_dcn = (const float*)d_in[4];
    (void)in_sizes; (void)n_in; (void)out_size;

    int prepack_total = 9 * 4096 + 9 * OC * 64;
    k_prepack<<<(prepack_total + 127) / 128, 128>>>(w_dcn, w_off);
    k_transpose<<<dim3(HW / 32, CI / 32, BN), dim3(32, 8)>>>(x);
    k_offcoef<<<BN * HW / 128, 256>>>(b_off);
    k_deform<<<BN * HW / 128, 256>>>(b_dcn, (float*)d_out);
}

// round 16
// speedup vs baseline: 1.5038x; 1.5038x over previous
#include <cuda_runtime.h>
#include <cuda_bf16.h>
#include <cstdint>

#define DEVFN __device__ __forceinline__

constexpr int BN = 16;      // batch
constexpr int CI = 64;      // in channels
constexpr int CO = 64;      // out channels
constexpr int HW = 4096;    // 64x64
constexpr int OC = 18;      // offset channels

// Scratch (static device memory; zero-initialized at module load)
__device__ __align__(16) float g_xt [BN * HW * CI];       // x in NHWC
__device__ __align__(16) __nv_bfloat16 g_wbh[9 * 4096];   // w_dcn hi, per-tap SW128-swizzled [co][cin]
__device__ __align__(16) __nv_bfloat16 g_wbl[9 * 4096];   // w_dcn lo
__device__ __align__(16) __nv_bfloat16 g_wobh[9 * 2048];  // w_off hi, per-tap SW128 [oc(32,pad0)][cin]
__device__ __align__(16) __nv_bfloat16 g_wobl[9 * 2048];  // w_off lo
__device__ __align__(16) float4 g_cfw[BN * HW * 9];       // bilinear weights per (pix,tap)
__device__ __align__(16) int4   g_cfi[BN * HW * 9];       // clamped corner base offsets

DEVFN uint32_t smem_u32(const void* p) {
    uint32_t a;
    asm("{ .reg .u64 t; cvta.to.shared.u64 t, %1; cvt.u32.u64 %0, t; }" : "=r"(a) : "l"(p));
    return a;
}
// ---- ldmatrix / mma.sync (sm_80+ PTX, valid on plain sm_103 target) ----
DEVFN void ldm_x4(uint32_t* r, uint32_t addr) {
    asm volatile("ldmatrix.sync.aligned.m8n8.x4.shared.b16 {%0,%1,%2,%3}, [%4];"
                 : "=r"(r[0]), "=r"(r[1]), "=r"(r[2]), "=r"(r[3]) : "r"(addr));
}
DEVFN void ldm_x2(uint32_t* r, uint32_t addr) {
    asm volatile("ldmatrix.sync.aligned.m8n8.x2.shared.b16 {%0,%1}, [%2];"
                 : "=r"(r[0]), "=r"(r[1]) : "r"(addr));
}
DEVFN void mma_bf16(float* d, const uint32_t* a, const uint32_t* b) {
    asm volatile("mma.sync.aligned.m16n8k16.row.col.f32.bf16.bf16.f32 "
                 "{%0,%1,%2,%3}, {%4,%5,%6,%7}, {%8,%9}, {%0,%1,%2,%3};"
                 : "+f"(d[0]), "+f"(d[1]), "+f"(d[2]), "+f"(d[3])
                 : "r"(a[0]), "r"(a[1]), "r"(a[2]), "r"(a[3]), "r"(b[0]), "r"(b[1]));
}
DEVFN uint32_t sw128(uint32_t byte) { return byte ^ ((byte >> 3) & 0x70); }
DEVFN void split_store(char* smem_base, uint32_t sw, float2 v, int loOff) {
    __nv_bfloat162 h2 = __float22bfloat162_rn(v);
    float2 fh = __bfloat1622float2(h2);
    __nv_bfloat162 l2 = __float22bfloat162_rn(make_float2(v.x - fh.x, v.y - fh.y));
    *(uint32_t*)(smem_base + sw)         = *(uint32_t*)&h2;
    *(uint32_t*)(smem_base + loOff + sw) = *(uint32_t*)&l2;
}

// ---------------------------------------------------------------------------
// Weight prepack: bf16 hi/lo split + SW128 pre-swizzle for both convs.
// ---------------------------------------------------------------------------
__global__ void k_prepack(const float* __restrict__ wdcn, const float* __restrict__ woff) {
    int i = blockIdx.x * blockDim.x + threadIdx.x;
    if (i < 9 * 4096) {
        int t = i >> 12, r = i & 4095;
        int co = r >> 6, cin = r & 63;
        float w = wdcn[(co * CI + cin) * 9 + t];
        __nv_bfloat16 hi = __float2bfloat16(w);
        __nv_bfloat16 lo = __float2bfloat16(w - __bfloat162float(hi));
        uint32_t sw = sw128((uint32_t)(co * 128 + cin * 2));
        g_wbh[t * 4096 + (sw >> 1)] = hi;
        g_wbl[t * 4096 + (sw >> 1)] = lo;
    }
    int j = i - 9 * 4096;
    if (j >= 0 && j < 9 * OC * 64) {
        int t  = j / (OC * 64);
        int r  = j - t * (OC * 64);
        int oc = r >> 6, cin = r & 63;
        float w = woff[(oc * CI + cin) * 9 + t];
        __nv_bfloat16 hi = __float2bfloat16(w);
        __nv_bfloat16 lo = __float2bfloat16(w - __bfloat162float(hi));
        uint32_t sw = sw128((uint32_t)(oc * 128 + cin * 2));
        g_wobh[t * 2048 + (sw >> 1)] = hi;
        g_wobl[t * 2048 + (sw >> 1)] = lo;
    }
}

// ---------------------------------------------------------------------------
// NCHW -> NHWC transpose
// ---------------------------------------------------------------------------
__global__ void k_transpose(const float* __restrict__ x) {
    __shared__ float s[32][33];
    int b  = blockIdx.z;
    int c0 = blockIdx.y * 32;
    int p0 = blockIdx.x * 32;
    int tx = threadIdx.x, ty = threadIdx.y;
    const float* xb = x + (size_t)b * CI * HW;
#pragma unroll
    for (int i = 0; i < 4; i++)
        s[ty + 8 * i][tx] = xb[(size_t)(c0 + ty + 8 * i) * HW + p0 + tx];
    __syncthreads();
    float* xtb = g_xt + (size_t)b * HW * CI;
#pragma unroll
    for (int i = 0; i < 4; i++)
        xtb[(size_t)(p0 + ty + 8 * i) * CI + c0 + tx] = s[tx][ty + 8 * i];
}

// ---------------------------------------------------------------------------
// Offset conv (split-bf16 mma, N padded 18->32) + fused bilinear coeff.
// CTA = 256 thr, 128 px. Coeff epilogue remapped: 1152 (pixel,tap) items
// assigned consecutively to threads -> coalesced g_cfw/g_cfi stores.
// smem: Ah[0,16K) Al[16K,32K) Bh[32K,36K) Bl[36K,40K); reused for epilogue.
// ---------------------------------------------------------------------------
__global__ __launch_bounds__(256) void k_offcoef(const float* __restrict__ boff) {
    __shared__ __align__(128) char smem[40960];
    uint32_t sb = smem_u32(smem);
    int tid = threadIdx.x, wid = tid >> 5, lane = tid & 31;
    int base = blockIdx.x * 128;
    int b    = base >> 12;
    int prow = base & 4095;
    const float* xtb = g_xt + (size_t)b * HW * CI;

    float acc[4][4];
#pragma unroll
    for (int ni = 0; ni < 4; ni++)
#pragma unroll
        for (int e = 0; e < 4; e++) acc[ni][e] = 0.f;

    for (int t = 0; t < 9; t++) {
        ((uint4*)(smem + 32768))[tid] = ((const uint4*)(g_wobh + t * 2048))[tid];
        ((uint4*)(smem + 36864))[tid] = ((const uint4*)(g_wobl + t * 2048))[tid];
        int dy = t / 3 - 1;
        int dx = t - (t / 3) * 3 - 1;
#pragma unroll 4
        for (int i = 0; i < 16; i++) {
            int p  = wid * 16 + i;
            int pp = prow + p;
            int y  = (pp >> 6) + dy;
            int x  = (pp & 63) + dx;
            float2 v = make_float2(0.f, 0.f);
            if (((unsigned)y < 64u) && ((unsigned)x < 64u))
                v = *((const float2*)(xtb + (((y << 6) + x) << 6)) + lane);
            split_store(smem, sw128((uint32_t)(p * 128 + lane * 4)), v, 16384);
        }
        __syncthreads();
#pragma unroll
        for (int k16 = 0; k16 < 4; k16++) {
            uint32_t ah[4], al[4];
            {
                int row = wid * 16 + (lane & 15);
                uint32_t byte = sw128((uint32_t)(row * 128 + k16 * 32 + ((lane >> 4) << 4)));
                ldm_x4(ah, sb + byte);
                ldm_x4(al, sb + 16384 + byte);
            }
            uint32_t bh[4][2], bl[4][2];
#pragma unroll
            for (int ni = 0; ni < 4; ni++) {
                int n = ni * 8 + (lane & 7);
                uint32_t byte = sw128((uint32_t)(n * 128 + k16 * 32 + (((lane >> 3) & 1) << 4)));
                ldm_x2(bh[ni], sb + 32768 + byte);
                ldm_x2(bl[ni], sb + 36864 + byte);
            }
#pragma unroll
            for (int ni = 0; ni < 4; ni++) {
                mma_bf16(acc[ni], ah, bh[ni]);
                mma_bf16(acc[ni], al, bh[ni]);
                mma_bf16(acc[ni], ah, bl[ni]);
            }
        }
        __syncthreads();
    }
    // ---- bounce offsets to smem [px][36] ----
    float* sAcc = (float*)smem;
    int r = lane >> 2, g = lane & 3;
#pragma unroll
    for (int ni = 0; ni < 4; ni++) {
        int co = ni * 8 + g * 2;
        int px = wid * 16 + r;
        sAcc[px * 36 + co]           = acc[ni][0];
        sAcc[px * 36 + co + 1]       = acc[ni][1];
        sAcc[(px + 8) * 36 + co]     = acc[ni][2];
        sAcc[(px + 8) * 36 + co + 1] = acc[ni][3];
    }
    __syncthreads();
    // ---- fused coeff, coalesced: item idx = p*9 + t, consecutive per thread ----
#pragma unroll
    for (int it = 0; it < 5; it++) {
        int idx = tid + 256 * it;              // 1152 items
        if (idx < 128 * 9) {
            int p = (idx * 0x1C72) >> 16;       // idx/9 for idx < 1152 (ceil(2^16*8/9 trick))
            p = idx / 9;                        // (compiler emits mul-shift; keep exact)
            int t = idx - p * 9;
            int pp = prow + p;
            float oy = sAcc[p * 36 + 2 * t]     + boff[2 * t];
            float ox = sAcc[p * 36 + 2 * t + 1] + boff[2 * t + 1];
            float py  = (float)((pp >> 6) + t / 3 - 1) + oy;
            float pxx = (float)((pp & 63) + t % 3 - 1) + ox;
            float y0f = floorf(py), x0f = floorf(pxx);
            float fy = py - y0f, fx = pxx - x0f;
            int y0 = (int)y0f, x0 = (int)x0f;
            float vy0 = ((unsigned)y0 < 64u) ? 1.f : 0.f;
            float vy1 = ((unsigned)(y0 + 1) < 64u) ? 1.f : 0.f;
            float vx0 = ((unsigned)x0 < 64u) ? 1.f : 0.f;
            float vx1 = ((unsigned)(x0 + 1) < 64u) ? 1.f : 0.f;
            float gy0 = 1.f - fy, gx0 = 1.f - fx;
            int gi = (base + p) * 9 + t;
            g_cfw[gi] = make_float4(gy0 * gx0 * vy0 * vx0, gy0 * fx * vy0 * vx1,
                                    fy * gx0 * vy1 * vx0,  fy * fx * vy1 * vx1);
            int yc0 = min(max(y0, 0), 63),     yc1 = min(max(y0 + 1, 0), 63);
            int xc0 = min(max(x0, 0), 63),     xc1 = min(max(x0 + 1, 0), 63);
            g_cfi[gi] = make_int4((((yc0 << 6) + xc0) << 6), (((yc0 << 6) + xc1) << 6),
                                  (((yc1 << 6) + xc0) << 6), (((yc1 << 6) + xc1) << 6));
        }
    }
}

// ---------------------------------------------------------------------------
// Deformable conv: split-bf16 mma.sync GEMM. CTA = 128 thr, 64 px x 64 co
// (4 warps, 2x2, warp tile 32x32). 92 regs x 128 thr -> 5 CTAs/SM (occ ~31%).
// smem: Ah[0,8K) Al[8K,16K) Bh[16K,24K) Bl[24K,32K); reused for epilogue.
// ---------------------------------------------------------------------------
__global__ __launch_bounds__(128) void k_deform(const float* __restrict__ bdcn,
                                                float* __restrict__ out) {
    __shared__ __align__(128) char smem[32768];
    uint32_t sb = smem_u32(smem);
    int tid = threadIdx.x, wid = tid >> 5, lane = tid & 31;
    int base = blockIdx.x * 64;
    int b    = base >> 12;
    int prow = base & 4095;
    const float* xtb = g_xt + (size_t)b * HW * CI;
    int wm = wid >> 1, wn = wid & 1;          // warp grid 2(m) x 2(n)
    int mbase = wm * 32, nbase = wn * 32;

    float acc[2][4][4];
#pragma unroll
    for (int mi = 0; mi < 2; mi++)
#pragma unroll
        for (int ni = 0; ni < 4; ni++)
#pragma unroll
            for (int e = 0; e < 4; e++) acc[mi][ni][e] = 0.f;

    for (int t = 0; t < 9; t++) {
        // ---- stage B hi/lo (pre-swizzled; 512 uint4 each, 4 per thread) ----
        {
            const uint4* sh = (const uint4*)(g_wbh + t * 4096);
            const uint4* sl = (const uint4*)(g_wbl + t * 4096);
#pragma unroll
            for (int r = 0; r < 4; r++) {
                ((uint4*)(smem + 16384))[tid + 128 * r] = sh[tid + 128 * r];
                ((uint4*)(smem + 24576))[tid + 128 * r] = sl[tid + 128 * r];
            }
        }
        // ---- bilinear gather: warp w -> pixels w*16..+15, lane = ch-pair ----
#pragma unroll 2
        for (int i = 0; i < 16; i++) {
            int p = wid * 16 + i;
            int ci = (base + p) * 9 + t;
            float4 cw = g_cfw[ci];
            int4  ii = g_cfi[ci];
            float2 v00 = *((const float2*)(xtb + ii.x) + lane);
            float2 v01 = *((const float2*)(xtb + ii.y) + lane);
            float2 v10 = *((const float2*)(xtb + ii.z) + lane);
            float2 v11 = *((const float2*)(xtb + ii.w) + lane);
            float2 v;
            v.x = cw.x * v00.x + cw.y * v01.x + cw.z * v10.x + cw.w * v11.x;
            v.y = cw.x * v00.y + cw.y * v01.y + cw.z * v10.y + cw.w * v11.y;
            split_store(smem, sw128((uint32_t)(p * 128 + lane * 4)), v, 8192);
        }
        __syncthreads();
        // ---- warp GEMM: 4 k16 chunks, 3 split passes on shared accumulators ----
#pragma unroll
        for (int k16 = 0; k16 < 4; k16++) {
            uint32_t ah[2][4], al[2][4];
#pragma unroll
            for (int mi = 0; mi < 2; mi++) {
                int row = mbase + mi * 16 + (lane & 15);
                uint32_t byte = sw128((uint32_t)(row * 128 + k16 * 32 + ((lane >> 4) << 4)));
                ldm_x4(ah[mi], sb + byte);
                ldm_x4(al[mi], sb + 8192 + byte);
            }
            uint32_t bh[4][2], bl[4][2];
#pragma unroll
            for (int ni = 0; ni < 4; ni++) {
                int n = nbase + ni * 8 + (lane & 7);
                uint32_t byte = sw128((uint32_t)(n * 128 + k16 * 32 + (((lane >> 3) & 1) << 4)));
                ldm_x2(bh[ni], sb + 16384 + byte);
                ldm_x2(bl[ni], sb + 24576 + byte);
            }
#pragma unroll
            for (int mi = 0; mi < 2; mi++)
#pragma unroll
                for (int ni = 0; ni < 4; ni++) {
                    mma_bf16(acc[mi][ni], ah[mi], bh[ni]);
                    mma_bf16(acc[mi][ni], al[mi], bh[ni]);
                    mma_bf16(acc[mi][ni], ah[mi], bl[ni]);
                }
        }
        __syncthreads();
    }
    // ---- epilogue: bounce acc through smem [co][68] for coalesced stores ----
    float* sAcc = (float*)smem;
    int r = lane >> 2, g = lane & 3;
#pragma unroll
    for (int mi = 0; mi < 2; mi++)
#pragma unroll
        for (int ni = 0; ni < 4; ni++) {
            int co = nbase + ni * 8 + g * 2;
            int px = mbase + mi * 16 + r;
            sAcc[co * 68 + px]             = acc[mi][ni][0];
            sAcc[(co + 1) * 68 + px]       = acc[mi][ni][1];
            sAcc[co * 68 + px + 8]         = acc[mi][ni][2];
            sAcc[(co + 1) * 68 + px + 8]   = acc[mi][ni][3];
        }
    __syncthreads();
    float* ob = out + (size_t)b * CO * HW + prow;
#pragma unroll
    for (int it = 0; it < 8; it++) {
        int idx = tid + 128 * it;          // 1024 float4 total
        int row = idx >> 4, c4 = idx & 15;
        float4 v = *(float4*)(sAcc + row * 68 + c4 * 4);
        float bias = bdcn[row];
        v.x += bias; v.y += bias; v.z += bias; v.w += bias;
        *(float4*)(ob + (size_t)row * HW + c4 * 4) = v;
    }
}

// ---------------------------------------------------------------------------
extern "C" void kernel_launch(void* const* d_in, const int* in_sizes, int n_in,
                              void* d_out, int out_size) {
    const float* x     = (const float*)d_in[0];
    const float* w_off = (const float*)d_in[1];
    const float* b_off = (const float*)d_in[2];
    const float* w_dcn = (const float*)d_in[3];
    const float* b_dcn = (const float*)d_in[4];
    (void)in_sizes; (void)n_in; (void)out_size;

    int prepack_total = 9 * 4096 + 9 * OC * 64;
    k_prepack<<<(prepack_total + 127) / 128, 128>>>(w_dcn, w_off);
    k_transpose<<<dim3(HW / 32, CI / 32, BN), dim3(32, 8)>>>(x);
    k_offcoef<<<BN * HW / 128, 256>>>(b_off);
    k_deform<<<BN * HW / 64, 128>>>(b_dcn, (float*)d_out);
}